// round 1
// baseline (speedup 1.0000x reference)
#include <cuda_runtime.h>
#include <math.h>

#define BB 8
#define H 256
#define W 256
#define NPIX (H*W)
#define BIGC 1e4f

// Scratch (device globals — no allocation allowed)
__device__ unsigned char g_bnd[BB*NPIX];
__device__ float         g_f2[BB*NPIX];
__device__ double        g_sum_pd[BB];
__device__ double        g_sum_d[BB];
__device__ unsigned int  g_max_d[BB];

__global__ void k_init() {
    int t = threadIdx.x;
    if (t < BB) { g_sum_pd[t] = 0.0; g_sum_d[t] = 0.0; g_max_d[t] = 0u; }
}

// boundary = tb XOR erode3x3(tb), erosion with zero padding (border erodes to false)
__global__ void k_boundary(const int* __restrict__ target) {
    int idx = blockIdx.x * blockDim.x + threadIdx.x;
    if (idx >= BB*NPIX) return;
    int b = idx / NPIX;
    int r = idx - b*NPIX;
    int i = r / W, j = r - (r / W) * W;
    const int* t = target + b*NPIX;
    bool tb = t[r] != 0;
    bool er;
    if (i == 0 || i == H-1 || j == 0 || j == W-1) {
        er = false;
    } else {
        er = tb
          && t[r - W - 1] && t[r - W] && t[r - W + 1]
          && t[r - 1]                 && t[r + 1]
          && t[r + W - 1] && t[r + W] && t[r + W + 1];
    }
    g_bnd[idx] = (unsigned char)(tb != er);
}

// Per-column vertical distance to nearest boundary seed, clipped at BIG, stored squared.
// One thread per (image, column); lockstep over rows -> fully coalesced.
__global__ void k_vert() {
    int b = blockIdx.x;
    int j = threadIdx.x;
    const unsigned char* bnd = g_bnd + b*NPIX;
    float* f2 = g_f2 + b*NPIX;
    int last = -1000000;
    for (int i = 0; i < H; i++) {
        int idx = i*W + j;
        if (bnd[idx]) last = i;
        f2[idx] = (float)(i - last);
    }
    int nxt = 1000000;
    for (int i = H-1; i >= 0; i--) {
        int idx = i*W + j;
        if (bnd[idx]) nxt = i;
        float f = fminf(f2[idx], (float)(nxt - i));
        f = fminf(f, BIGC);
        f2[idx] = f * f;
    }
}

// One block per row: exact min-plus over columns, fused with sigmoid + reductions.
// d[j] = sqrt(min_j' f2[j'] + (j-j')^2); accumulate sum(pred*d), sum(d), max(d) per image.
__global__ void __launch_bounds__(W) k_row(const float* __restrict__ logits) {
    __shared__ float s[W];
    int row = blockIdx.x;          // 0..BB*H-1
    int b = row / H;
    int j = threadIdx.x;
    int base = row * W;
    s[j] = g_f2[base + j];
    __syncthreads();

    const float4* s4 = (const float4*)s;
    float t = (float)j;
    float m0 = 3e38f, m1 = 3e38f, m2 = 3e38f, m3 = 3e38f;
    #pragma unroll 8
    for (int k = 0; k < W/4; k++) {
        float4 v = s4[k];
        float t1 = t - 1.f, t2 = t - 2.f, t3 = t - 3.f;
        m0 = fminf(m0, fmaf(t,  t,  v.x));
        m1 = fminf(m1, fmaf(t1, t1, v.y));
        m2 = fminf(m2, fmaf(t2, t2, v.z));
        m3 = fminf(m3, fmaf(t3, t3, v.w));
        t -= 4.f;
    }
    float m = fminf(fminf(m0, m1), fminf(m2, m3));
    float d = sqrtf(m);

    float x = logits[base + j];
    float pred = 1.f / (1.f + expf(-x));
    float pd = pred * d;

    // intra-warp reduction
    float sd = d, spd = pd, mx = d;
    #pragma unroll
    for (int o = 16; o; o >>= 1) {
        sd  += __shfl_down_sync(0xffffffffu, sd,  o);
        spd += __shfl_down_sync(0xffffffffu, spd, o);
        mx   = fmaxf(mx, __shfl_down_sync(0xffffffffu, mx, o));
    }
    __shared__ float rs[8], rp[8], rm[8];
    int lane = j & 31, wrp = j >> 5;
    if (lane == 0) { rs[wrp] = sd; rp[wrp] = spd; rm[wrp] = mx; }
    __syncthreads();
    if (j == 0) {
        float S = 0.f, P = 0.f, M = 0.f;
        #pragma unroll
        for (int w2 = 0; w2 < 8; w2++) { S += rs[w2]; P += rp[w2]; M = fmaxf(M, rm[w2]); }
        atomicAdd(&g_sum_d[b],  (double)S);
        atomicAdd(&g_sum_pd[b], (double)P);
        atomicMax(&g_max_d[b], __float_as_uint(M));  // d >= 0, bit order == float order
    }
}

// per = Sp / (Sd + 1e-7*(M+1e-7))  ==  sum(pred*dn)/(sum(dn)+1e-7) with dn=d/(M+1e-7)
__global__ void k_final(float* out) {
    if (threadIdx.x == 0 && blockIdx.x == 0) {
        double acc = 0.0;
        for (int b = 0; b < BB; b++) {
            double M = (double)__uint_as_float(g_max_d[b]);
            double per = g_sum_pd[b] / (g_sum_d[b] + 1e-7 * (M + 1e-7));
            acc += per;
        }
        out[0] = (float)(acc / BB);
    }
}

extern "C" void kernel_launch(void* const* d_in, const int* in_sizes, int n_in,
                              void* d_out, int out_size) {
    const float* logits = (const float*)d_in[0];
    const int*   target = (const int*)d_in[1];
    float* out = (float*)d_out;

    k_init<<<1, 32>>>();
    k_boundary<<<(BB*NPIX + 255) / 256, 256>>>(target);
    k_vert<<<BB, W>>>();
    k_row<<<BB*H, W>>>(logits);
    k_final<<<1, 1>>>(out);
}

// round 2
// speedup vs baseline: 2.1875x; 2.1875x over previous
#include <cuda_runtime.h>
#include <math.h>

#define BB 8
#define H 256
#define W 256
#define NPIX (H*W)
#define BIGC 1e4f
#define NROWS (BB*H)

// Scratch (device globals — no allocation allowed)
__device__ float g_f2[BB*NPIX];     // squared vertical distance, clipped
__device__ float g_pd[NROWS];       // per-row sum(pred*d)
__device__ float g_d [NROWS];       // per-row sum(d)
__device__ float g_mx[NROWS];       // per-row max(d)

// ---------------------------------------------------------------------------
// k_prep: one block per image. Build tb bitmask, 3x3 erosion via bit ops,
// boundary = tb ^ er, then per-column vertical EDT (clipped, squared) -> g_f2.
// ---------------------------------------------------------------------------
__global__ void __launch_bounds__(256) k_prep(const int* __restrict__ target) {
    __shared__ unsigned int tb[H][8];   // bit j%32 of word j/32 = tb(i,j)
    __shared__ unsigned int hm[H][8];   // horizontal 3-AND
    __shared__ unsigned int bd[H][8];   // boundary bits

    int b = blockIdx.x;
    int tid = threadIdx.x;
    int lane = tid & 31, w = tid >> 5;
    const int* t = target + b * NPIX;

    // Phase A: ballot-pack target into bitmasks (warp w does rows w, w+8, ...)
    for (int i = w; i < H; i += 8) {
        #pragma unroll
        for (int g = 0; g < 8; g++) {
            int v = t[i * W + g * 32 + lane];
            unsigned int mask = __ballot_sync(0xffffffffu, v != 0);
            if (lane == 0) tb[i][g] = mask;
        }
    }
    __syncthreads();

    // Phase B1: horizontal 3-wide AND (left/right neighbors; borders handled later)
    for (int k = tid; k < H * 8; k += 256) {
        int i = k >> 3, g = k & 7;
        unsigned int c = tb[i][g];
        unsigned int l = (c << 1) | (g > 0 ? (tb[i][g - 1] >> 31) : 0u);
        unsigned int r = (c >> 1) | (g < 7 ? (tb[i][g + 1] << 31) : 0u);
        hm[i][g] = c & l & r;
    }
    __syncthreads();

    // Phase B2: vertical 3-AND -> erosion; border rows/cols erode to false.
    for (int k = tid; k < H * 8; k += 256) {
        int i = k >> 3, g = k & 7;
        unsigned int er;
        if (i == 0 || i == H - 1) er = 0u;
        else er = hm[i - 1][g] & hm[i][g] & hm[i + 1][g];
        if (g == 0) er &= ~1u;
        if (g == 7) er &= ~(1u << 31);
        bd[i][g] = tb[i][g] ^ er;
    }
    __syncthreads();

    // Phase C: vertical EDT per column (thread = column). Warp reads one shared
    // word per row (broadcast). Forward pass writes raw up-distance; backward
    // pass combines, clips, squares.
    int j = tid;
    int wj = j >> 5, bp = j & 31;
    float* f2 = g_f2 + b * NPIX;
    int last = -(1 << 20);
    for (int i = 0; i < H; i++) {
        if ((bd[i][wj] >> bp) & 1u) last = i;
        f2[i * W + j] = (float)(i - last);
    }
    int nxt = (1 << 20);
    for (int i = H - 1; i >= 0; i--) {
        if ((bd[i][wj] >> bp) & 1u) nxt = i;
        float f = fminf(f2[i * W + j], (float)(nxt - i));
        f = fminf(f, BIGC);
        f2[i * W + j] = f * f;
    }
}

// ---------------------------------------------------------------------------
// k_row: one block per row. Exact min-plus with outward early-exit search:
// once off^2 >= current min, no farther candidate can win (f2 >= 0).
// Warp-uniform break via __all_sync. Then sigmoid + per-row reductions.
// ---------------------------------------------------------------------------
__global__ void __launch_bounds__(W) k_row(const float* __restrict__ logits) {
    __shared__ float s[3 * W];          // padded: [0,W) and [2W,3W) are +inf pads
    int row = blockIdx.x;               // 0..NROWS-1
    int j = threadIdx.x;
    int base = row * W;

    s[j] = 1e30f;
    s[2 * W + j] = 1e30f;
    s[W + j] = g_f2[base + j];
    __syncthreads();

    float m = s[W + j];
    float off = 1.f;
    #pragma unroll 1
    for (int o = 1; o < W; o++) {
        float o2 = off * off;
        if (__all_sync(0xffffffffu, o2 >= m)) break;
        m = fminf(m, s[W + j - o] + o2);
        m = fminf(m, s[W + j + o] + o2);
        off += 1.f;
    }
    float d = sqrtf(m);

    float x = logits[base + j];
    float pred = 1.f / (1.f + __expf(-x));
    float pd = pred * d;

    // deterministic intra-block reduction
    float sd = d, spd = pd, mx = d;
    #pragma unroll
    for (int o = 16; o; o >>= 1) {
        sd  += __shfl_down_sync(0xffffffffu, sd,  o);
        spd += __shfl_down_sync(0xffffffffu, spd, o);
        mx   = fmaxf(mx, __shfl_down_sync(0xffffffffu, mx, o));
    }
    __shared__ float rs[8], rp[8], rm[8];
    int lane = j & 31, wrp = j >> 5;
    if (lane == 0) { rs[wrp] = sd; rp[wrp] = spd; rm[wrp] = mx; }
    __syncthreads();
    if (j == 0) {
        float S = 0.f, P = 0.f, M = 0.f;
        #pragma unroll
        for (int w2 = 0; w2 < 8; w2++) { S += rs[w2]; P += rp[w2]; M = fmaxf(M, rm[w2]); }
        g_d[row] = S; g_pd[row] = P; g_mx[row] = M;
    }
}

// ---------------------------------------------------------------------------
// k_final: 1 block, 256 threads. Warp b reduces image b's 256 row-partials
// deterministically; thread 0 averages.
//   per = Sp / (Sd + 1e-7*(M+1e-7))  ==  sum(pred*dn)/(sum(dn)+1e-7)
// ---------------------------------------------------------------------------
__global__ void __launch_bounds__(256) k_final(float* __restrict__ out) {
    __shared__ double sper[BB];
    int tid = threadIdx.x;
    int lane = tid & 31, b = tid >> 5;   // 8 warps = 8 images

    double sd = 0.0, sp = 0.0;
    float mx = 0.f;
    #pragma unroll
    for (int k = 0; k < 8; k++) {
        int r = b * H + k * 32 + lane;
        sd += (double)g_d[r];
        sp += (double)g_pd[r];
        mx = fmaxf(mx, g_mx[r]);
    }
    #pragma unroll
    for (int o = 16; o; o >>= 1) {
        sd += __shfl_down_sync(0xffffffffu, sd, o);
        sp += __shfl_down_sync(0xffffffffu, sp, o);
        mx  = fmaxf(mx, __shfl_down_sync(0xffffffffu, mx, o));
    }
    if (lane == 0)
        sper[b] = sp / (sd + 1e-7 * ((double)mx + 1e-7));
    __syncthreads();
    if (tid == 0) {
        double acc = 0.0;
        #pragma unroll
        for (int k = 0; k < BB; k++) acc += sper[k];
        out[0] = (float)(acc / BB);
    }
}

extern "C" void kernel_launch(void* const* d_in, const int* in_sizes, int n_in,
                              void* d_out, int out_size) {
    const float* logits = (const float*)d_in[0];
    const int*   target = (const int*)d_in[1];
    float* out = (float*)d_out;

    k_prep<<<BB, 256>>>(target);
    k_row<<<NROWS, W>>>(logits);
    k_final<<<1, 256>>>(out);
}

// round 3
// speedup vs baseline: 5.8917x; 2.6933x over previous
#include <cuda_runtime.h>
#include <math.h>

#define BB 8
#define H 256
#define W 256
#define NPIX (H*W)
#define NROWS (BB*H)

// Scratch (device globals — no allocation allowed)
__device__ unsigned int g_tb[BB*H*8];   // packed target bits: word (b,i,g), bit j%32
__device__ float g_f2[BB*NPIX];         // squared vertical distance, clipped
__device__ float g_pd[NROWS];           // per-row sum(pred*d)
__device__ float g_d [NROWS];           // per-row sum(d)
__device__ float g_mx[NROWS];           // per-row max(d)

// ---------------------------------------------------------------------------
// k_pack: ballot-pack target into bitmasks. One thread per pixel, 16K warps.
// ---------------------------------------------------------------------------
__global__ void k_pack(const int* __restrict__ target) {
    int p = blockIdx.x * 256 + threadIdx.x;         // 0 .. BB*NPIX-1
    unsigned int m = __ballot_sync(0xffffffffu, target[p] != 0);
    if ((threadIdx.x & 31) == 0) g_tb[p >> 5] = m;
}

// ---------------------------------------------------------------------------
// k_vedt: block = (image b, word-group g) -> 32 columns, all 256 rows.
//  Phase 1: boundary word per row (tb ^ erode3x3) from 9 L2-hot word loads.
//  Phase 2: warp ballot-transpose -> lane j holds column j's seed bits for
//           its warp's 32-row slab.
//  Phase 3: cross-slab prefix (8 steps) + clz/ffs per row -> exact vertical
//           distance, clipped at 1e4, squared, stored row-major (coalesced).
// ---------------------------------------------------------------------------
__global__ void __launch_bounds__(256) k_vedt() {
    __shared__ unsigned int bd_s[H];
    __shared__ unsigned int colmask[8][32];

    int b = blockIdx.x >> 3;
    int g = blockIdx.x & 7;
    int tid = threadIdx.x;
    const unsigned int* tb = g_tb + b * H * 8;

    // Phase 1: boundary word for row i = tid
    {
        int i = tid;
        unsigned int c = tb[i * 8 + g];
        unsigned int er = 0u;
        if (i > 0 && i < H - 1) {
            unsigned int h[3];
            #pragma unroll
            for (int r = 0; r < 3; r++) {
                int ir = i - 1 + r;
                unsigned int cc = tb[ir * 8 + g];
                unsigned int lf = (cc << 1) | (g > 0 ? (tb[ir * 8 + g - 1] >> 31) : 0u);
                unsigned int rt = (cc >> 1) | (g < 7 ? (tb[ir * 8 + g + 1] << 31) : 0u);
                h[r] = cc & lf & rt;   // horizontal 3-AND (borders shift in 0)
            }
            er = h[0] & h[1] & h[2];   // vertical 3-AND
        }
        bd_s[i] = c ^ er;
    }
    __syncthreads();

    // Phase 2: 32x32 bit transpose within each warp (warp w = rows 32w..32w+31)
    int w = tid >> 5, lane = tid & 31;
    unsigned int word = bd_s[(w << 5) + lane];
    unsigned int v = 0u;
    #pragma unroll
    for (int j = 0; j < 32; j++) {
        unsigned int bm = __ballot_sync(0xffffffffu, (word >> j) & 1u);
        if (lane == j) v = bm;        // lane j: column j's bits over this slab
    }
    colmask[w][lane] = v;
    __syncthreads();

    // Phase 3: cross-slab nearest-seed info for this (slab w, column lane)
    int P = -1000000;                 // last seed row in slabs < w
    int N =  1000000;                 // first seed row in slabs > w
    #pragma unroll
    for (int k = 0; k < 8; k++) {
        unsigned int vk = colmask[k][lane];
        if (k < w && vk) P = (k << 5) + 31 - __clz(vk);
        if (k > w && vk && N == 1000000) N = (k << 5) + __ffs(vk) - 1;
    }

    float* f2 = g_f2 + b * NPIX + (g << 5) + lane;
    int rowbase = w << 5;
    #pragma unroll
    for (int r = 0; r < 32; r++) {
        unsigned int below = v & (0xFFFFFFFFu >> (31 - r));  // bits 0..r
        unsigned int above = v & (0xFFFFFFFFu << r);         // bits r..31
        int row = rowbase + r;
        int last = below ? (rowbase + 31 - __clz(below)) : P;
        int nxt  = above ? (rowbase + __ffs(above) - 1)  : N;
        int up = row - last, dn = nxt - row;
        int f = min(min(up, dn), 10000);                     // BIG clip (1e4)
        f2[row * W] = (float)(f * f);                        // exact (1e8 fits fp32)
    }
}

// ---------------------------------------------------------------------------
// k_row: one block per row. Exact min-plus with outward early-exit search:
// once off^2 >= current min, no farther candidate can win (f2 >= 0).
// Warp-uniform break via __all_sync. Then sigmoid + per-row reductions.
// ---------------------------------------------------------------------------
__global__ void __launch_bounds__(W) k_row(const float* __restrict__ logits) {
    __shared__ float s[3 * W];          // [0,W) and [2W,3W) are +inf pads
    int row = blockIdx.x;               // 0..NROWS-1
    int j = threadIdx.x;
    int base = row * W;

    s[j] = 1e30f;
    s[2 * W + j] = 1e30f;
    s[W + j] = g_f2[base + j];
    __syncthreads();

    float m = s[W + j];
    float off = 1.f;
    #pragma unroll 1
    for (int o = 1; o < W; o++) {
        float o2 = off * off;
        if (__all_sync(0xffffffffu, o2 >= m)) break;
        m = fminf(m, s[W + j - o] + o2);
        m = fminf(m, s[W + j + o] + o2);
        off += 1.f;
    }
    float d = sqrtf(m);

    float x = logits[base + j];
    float pred = 1.f / (1.f + __expf(-x));
    float pd = pred * d;

    // deterministic intra-block reduction
    float sd = d, spd = pd, mx = d;
    #pragma unroll
    for (int o = 16; o; o >>= 1) {
        sd  += __shfl_down_sync(0xffffffffu, sd,  o);
        spd += __shfl_down_sync(0xffffffffu, spd, o);
        mx   = fmaxf(mx, __shfl_down_sync(0xffffffffu, mx, o));
    }
    __shared__ float rs[8], rp[8], rm[8];
    int lane = j & 31, wrp = j >> 5;
    if (lane == 0) { rs[wrp] = sd; rp[wrp] = spd; rm[wrp] = mx; }
    __syncthreads();
    if (j == 0) {
        float S = 0.f, P = 0.f, M = 0.f;
        #pragma unroll
        for (int w2 = 0; w2 < 8; w2++) { S += rs[w2]; P += rp[w2]; M = fmaxf(M, rm[w2]); }
        g_d[row] = S; g_pd[row] = P; g_mx[row] = M;
    }
}

// ---------------------------------------------------------------------------
// k_final: 1 block, 256 threads. Warp b reduces image b's 256 row-partials
// deterministically; thread 0 averages.
//   per = Sp / (Sd + 1e-7*(M+1e-7))  ==  sum(pred*dn)/(sum(dn)+1e-7)
// ---------------------------------------------------------------------------
__global__ void __launch_bounds__(256) k_final(float* __restrict__ out) {
    __shared__ double sper[BB];
    int tid = threadIdx.x;
    int lane = tid & 31, b = tid >> 5;   // 8 warps = 8 images

    double sd = 0.0, sp = 0.0;
    float mx = 0.f;
    #pragma unroll
    for (int k = 0; k < 8; k++) {
        int r = b * H + k * 32 + lane;
        sd += (double)g_d[r];
        sp += (double)g_pd[r];
        mx = fmaxf(mx, g_mx[r]);
    }
    #pragma unroll
    for (int o = 16; o; o >>= 1) {
        sd += __shfl_down_sync(0xffffffffu, sd, o);
        sp += __shfl_down_sync(0xffffffffu, sp, o);
        mx  = fmaxf(mx, __shfl_down_sync(0xffffffffu, mx, o));
    }
    if (lane == 0)
        sper[b] = sp / (sd + 1e-7 * ((double)mx + 1e-7));
    __syncthreads();
    if (tid == 0) {
        double acc = 0.0;
        #pragma unroll
        for (int k = 0; k < BB; k++) acc += sper[k];
        out[0] = (float)(acc / BB);
    }
}

extern "C" void kernel_launch(void* const* d_in, const int* in_sizes, int n_in,
                              void* d_out, int out_size) {
    const float* logits = (const float*)d_in[0];
    const int*   target = (const int*)d_in[1];
    float* out = (float*)d_out;

    k_pack<<<BB * NPIX / 256, 256>>>(target);
    k_vedt<<<BB * 8, 256>>>();
    k_row<<<NROWS, W>>>(logits);
    k_final<<<1, 256>>>(out);
}

// round 4
// speedup vs baseline: 5.9814x; 1.0152x over previous
#include <cuda_runtime.h>
#include <math.h>

#define BB 8
#define H 256
#define W 256
#define NPIX (H*W)
#define NROWS (BB*H)

// Scratch (device globals — no allocation allowed)
__device__ float g_f2[BB*NPIX];         // squared vertical distance, clipped
__device__ float g_pd[NROWS];           // per-row sum(pred*d)
__device__ float g_d [NROWS];           // per-row sum(d)
__device__ float g_mx[NROWS];           // per-row max(d)
__device__ unsigned int g_ticket = 0;   // last-block-done counter (reset by last block)

// ---------------------------------------------------------------------------
// k_pv: block = (image b, word-group g) -> 32 columns, all 256 rows.
//  Phase A: ballot-pack target stripe (+halo cols) into bitmasks in shared.
//  Phase B: boundary = tb ^ erode3x3 via bit ops.
//  Phase C: warp ballot-transpose -> lane j holds column j's seed bits per slab.
//  Phase D: cross-slab prefix + clz/ffs -> exact vertical distance, clipped,
//           squared, stored row-major (coalesced).
// ---------------------------------------------------------------------------
__global__ void __launch_bounds__(256) k_pv(const int* __restrict__ target) {
    __shared__ unsigned int tb_s[H];        // packed target bits for this stripe
    __shared__ unsigned int hm_s[H];        // horizontal 3-AND
    __shared__ unsigned int Lm[8], Rm[8];   // halo column bits (rows packed)
    __shared__ unsigned int colmask[8][32]; // transposed boundary bits

    int b = blockIdx.x >> 3;
    int g = blockIdx.x & 7;
    int tid = threadIdx.x, w = tid >> 5, lane = tid & 31;
    const int* t = target + b * NPIX;
    int colbase = g << 5;

    // Phase A: warp w packs rows 32w..32w+31 (coalesced 128B per row)
    #pragma unroll 8
    for (int r = 0; r < 32; r++) {
        int i = (w << 5) + r;
        int v = t[i * W + colbase + lane];
        unsigned int m = __ballot_sync(0xffffffffu, v != 0);
        if (lane == 0) tb_s[i] = m;
    }
    // Halo columns: lane = row within slab
    {
        int i = (w << 5) + lane;
        int Lv = (g > 0) ? t[i * W + colbase - 1]  : 0;
        int Rv = (g < 7) ? t[i * W + colbase + 32] : 0;
        unsigned int lm = __ballot_sync(0xffffffffu, Lv != 0);
        unsigned int rm = __ballot_sync(0xffffffffu, Rv != 0);
        if (lane == 0) { Lm[w] = lm; Rm[w] = rm; }
    }
    __syncthreads();

    // Phase B1: horizontal 3-AND per row (thread = row)
    {
        int i = tid;
        unsigned int c  = tb_s[i];
        unsigned int Lb = (Lm[i >> 5] >> (i & 31)) & 1u;
        unsigned int Rb = (Rm[i >> 5] >> (i & 31)) & 1u;
        unsigned int lf = (c << 1) | Lb;
        unsigned int rt = (c >> 1) | (Rb << 31);
        hm_s[i] = c & lf & rt;
    }
    __syncthreads();

    // Phase B2: vertical 3-AND -> erosion; border rows/cols erode to false.
    unsigned int bdw;
    {
        int i = tid;
        unsigned int er = (i > 0 && i < H - 1)
                        ? (hm_s[i - 1] & hm_s[i] & hm_s[i + 1]) : 0u;
        if (g == 0) er &= ~1u;
        if (g == 7) er &= ~(1u << 31);
        bdw = tb_s[i] ^ er;
    }
    __syncthreads();
    tb_s[tid] = bdw;                       // reuse as boundary array
    __syncthreads();

    // Phase C: 32x32 bit transpose within each warp (warp w = rows 32w..32w+31)
    unsigned int word = tb_s[(w << 5) + lane];
    unsigned int v = 0u;
    #pragma unroll
    for (int j = 0; j < 32; j++) {
        unsigned int bm = __ballot_sync(0xffffffffu, (word >> j) & 1u);
        if (lane == j) v = bm;             // lane j: column j's bits over slab
    }
    colmask[w][lane] = v;
    __syncthreads();

    // Phase D: nearest seed outside this slab for column 'lane'
    int P = -1000000, N = 1000000;
    #pragma unroll
    for (int k = 0; k < 8; k++) {
        unsigned int vk = colmask[k][lane];
        if (k < w && vk) P = (k << 5) + 31 - __clz(vk);
        if (k > w && vk && N == 1000000) N = (k << 5) + __ffs(vk) - 1;
    }

    float* f2 = g_f2 + b * NPIX + colbase + lane;
    int rowbase = w << 5;
    #pragma unroll
    for (int r = 0; r < 32; r++) {
        unsigned int below = v & (0xFFFFFFFFu >> (31 - r));
        unsigned int above = v & (0xFFFFFFFFu << r);
        int row = rowbase + r;
        int last = below ? (rowbase + 31 - __clz(below)) : P;
        int nxt  = above ? (rowbase + __ffs(above) - 1)  : N;
        int f = min(min(row - last, nxt - row), 10000);   // BIG clip (1e4)
        f2[row * W] = (float)(f * f);                     // exact in fp32
    }
}

// ---------------------------------------------------------------------------
// k_rowfin: one block per row. Exact min-plus with outward early-exit search,
// sigmoid + per-row reductions; last finished block does the final reduce.
// ---------------------------------------------------------------------------
__global__ void __launch_bounds__(W) k_rowfin(const float* __restrict__ logits,
                                              float* __restrict__ out) {
    __shared__ float s[3 * W];              // [0,W) and [2W,3W) are +inf pads
    int row = blockIdx.x;                   // 0..NROWS-1
    int j = threadIdx.x;
    int base = row * W;

    s[j] = 1e30f;
    s[2 * W + j] = 1e30f;
    s[W + j] = g_f2[base + j];
    __syncthreads();

    float m = s[W + j];
    float off = 1.f;
    #pragma unroll 1
    for (int o = 1; o < W; o++) {
        float o2 = off * off;
        if (__all_sync(0xffffffffu, o2 >= m)) break;
        m = fminf(m, s[W + j - o] + o2);
        m = fminf(m, s[W + j + o] + o2);
        off += 1.f;
    }
    float d = sqrtf(m);

    float x = logits[base + j];
    float pred = 1.f / (1.f + __expf(-x));
    float pd = pred * d;

    // deterministic intra-block reduction
    float sd = d, spd = pd, mx = d;
    #pragma unroll
    for (int o = 16; o; o >>= 1) {
        sd  += __shfl_down_sync(0xffffffffu, sd,  o);
        spd += __shfl_down_sync(0xffffffffu, spd, o);
        mx   = fmaxf(mx, __shfl_down_sync(0xffffffffu, mx, o));
    }
    __shared__ float rs[8], rp[8], rm[8];
    int lane = j & 31, wrp = j >> 5;
    if (lane == 0) { rs[wrp] = sd; rp[wrp] = spd; rm[wrp] = mx; }
    __syncthreads();

    __shared__ bool amLast;
    if (j == 0) {
        float S = 0.f, P = 0.f, M = 0.f;
        #pragma unroll
        for (int w2 = 0; w2 < 8; w2++) { S += rs[w2]; P += rp[w2]; M = fmaxf(M, rm[w2]); }
        g_d[row] = S; g_pd[row] = P; g_mx[row] = M;
        __threadfence();
        unsigned int t = atomicAdd(&g_ticket, 1u);
        amLast = (t == NROWS - 1);
    }
    __syncthreads();
    if (!amLast) return;

    // ---- last block: final deterministic reduction (same order as before) ----
    int b = j >> 5;                         // 8 warps = 8 images
    double sdd = 0.0, spp = 0.0;
    float mxx = 0.f;
    #pragma unroll
    for (int k = 0; k < 8; k++) {
        int r = b * H + k * 32 + lane;
        sdd += (double)g_d[r];
        spp += (double)g_pd[r];
        mxx = fmaxf(mxx, g_mx[r]);
    }
    #pragma unroll
    for (int o = 16; o; o >>= 1) {
        sdd += __shfl_down_sync(0xffffffffu, sdd, o);
        spp += __shfl_down_sync(0xffffffffu, spp, o);
        mxx  = fmaxf(mxx, __shfl_down_sync(0xffffffffu, mxx, o));
    }
    __shared__ double sper[BB];
    if (lane == 0)
        sper[b] = spp / (sdd + 1e-7 * ((double)mxx + 1e-7));
    __syncthreads();
    if (j == 0) {
        double acc = 0.0;
        #pragma unroll
        for (int k = 0; k < BB; k++) acc += sper[k];
        out[0] = (float)(acc / BB);
        g_ticket = 0;                       // reset for next graph replay
    }
}

extern "C" void kernel_launch(void* const* d_in, const int* in_sizes, int n_in,
                              void* d_out, int out_size) {
    const float* logits = (const float*)d_in[0];
    const int*   target = (const int*)d_in[1];
    float* out = (float*)d_out;

    k_pv<<<BB * 8, 256>>>(target);
    k_rowfin<<<NROWS, W>>>(logits, out);
}

// round 5
// speedup vs baseline: 7.6185x; 1.2737x over previous
#include <cuda_runtime.h>
#include <math.h>

#define BB 8
#define H 256
#define W 256
#define NPIX (H*W)
#define GRID 512
#define PREP_BLOCKS 64

// Scratch (device globals — no allocation allowed)
__device__ unsigned int g_cm[BB*W*8];   // column seed masks: [(b*W+j)*8 + slab]
__device__ float g_pd[GRID];            // per-block sum(pred*d)
__device__ float g_d [GRID];            // per-block sum(d)
__device__ float g_mx[GRID];            // per-block max(d)
__device__ unsigned int g_barA = 0;     // phase-A arrival counter
__device__ unsigned int g_ticket = 0;   // phase-B completion counter

union SmemU {
    struct {                            // phase A
        unsigned int tb[H];
        unsigned int hm[H];
        unsigned int Lm[8], Rm[8];
    } a;
    struct {                            // phase B: 4 rows, each padded [W|W|W]
        float s[4][3*W];
    } b;
};

__global__ void __launch_bounds__(256, 4)
k_fused(const float* __restrict__ logits, const int* __restrict__ target,
        float* __restrict__ out) {
    __shared__ SmemU u;
    __shared__ float rs[8], rp[8], rm[8];
    __shared__ bool amLast;

    int bid = blockIdx.x;
    int tid = threadIdx.x;
    int w = tid >> 5, lane = tid & 31;

    // ================= Phase A: boundary bitmasks -> g_cm (blocks 0..63) ====
    if (bid < PREP_BLOCKS) {
        int b = bid >> 3;
        int g = bid & 7;
        const int* t = target + b * NPIX;
        int colbase = g << 5;

        // pack target stripe: warp w packs rows 32w..32w+31 (coalesced)
        #pragma unroll 8
        for (int r = 0; r < 32; r++) {
            int i = (w << 5) + r;
            int v = t[i * W + colbase + lane];
            unsigned int m = __ballot_sync(0xffffffffu, v != 0);
            if (lane == 0) u.a.tb[i] = m;
        }
        // halo columns (lane = row within slab)
        {
            int i = (w << 5) + lane;
            int Lv = (g > 0) ? t[i * W + colbase - 1]  : 0;
            int Rv = (g < 7) ? t[i * W + colbase + 32] : 0;
            unsigned int lm = __ballot_sync(0xffffffffu, Lv != 0);
            unsigned int rm2 = __ballot_sync(0xffffffffu, Rv != 0);
            if (lane == 0) { u.a.Lm[w] = lm; u.a.Rm[w] = rm2; }
        }
        __syncthreads();

        // horizontal 3-AND (thread = row)
        {
            int i = tid;
            unsigned int c  = u.a.tb[i];
            unsigned int Lb = (u.a.Lm[i >> 5] >> (i & 31)) & 1u;
            unsigned int Rb = (u.a.Rm[i >> 5] >> (i & 31)) & 1u;
            unsigned int lf = (c << 1) | Lb;
            unsigned int rt = (c >> 1) | (Rb << 31);
            u.a.hm[i] = c & lf & rt;
        }
        __syncthreads();

        // vertical 3-AND -> erosion; boundary = tb ^ er (borders erode false)
        unsigned int bdw;
        {
            int i = tid;
            unsigned int er = (i > 0 && i < H - 1)
                            ? (u.a.hm[i - 1] & u.a.hm[i] & u.a.hm[i + 1]) : 0u;
            if (g == 0) er &= ~1u;
            if (g == 7) er &= ~(1u << 31);
            bdw = u.a.tb[i] ^ er;
        }
        __syncthreads();
        u.a.tb[tid] = bdw;
        __syncthreads();

        // 32x32 bit transpose per warp; lane j gets column j's slab bits
        unsigned int word = u.a.tb[(w << 5) + lane];
        unsigned int v = 0u;
        #pragma unroll
        for (int jj = 0; jj < 32; jj++) {
            unsigned int bm = __ballot_sync(0xffffffffu, (word >> jj) & 1u);
            if (lane == jj) v = bm;
        }
        // publish: column (colbase+lane), slab w
        g_cm[((b * W) + colbase + lane) * 8 + w] = v;

        __threadfence();
        __syncthreads();
        if (tid == 0) atomicAdd(&g_barA, 1u);
    }

    // ================= Grid barrier (all 512 blocks co-resident) ===========
    if (tid == 0) {
        while (atomicAdd(&g_barA, 0u) < PREP_BLOCKS) __nanosleep(40);
    }
    __syncthreads();

    // ================= Phase B: 4 rows per block =============================
    int b = bid >> 6;                   // image
    int i0 = (bid & 63) * 4;            // first row of this group (same slab)
    int j = tid;                        // column

    // column seed mask (256 bits) for column j
    const uint4* cmp = (const uint4*)&g_cm[((b * W) + j) * 8];
    uint4 lov = cmp[0], hiv = cmp[1];
    unsigned int cm[8] = {lov.x, lov.y, lov.z, lov.w, hiv.x, hiv.y, hiv.z, hiv.w};

    int ws = i0 >> 5;
    int P = -1000000, N = 1000000;
    #pragma unroll
    for (int k = 0; k < 8; k++) {
        if (k < ws && cm[k]) P = (k << 5) + 31 - __clz(cm[k]);
        if (k > ws && cm[k] && N == 1000000) N = (k << 5) + __ffs(cm[k]) - 1;
    }
    unsigned int vw = cm[ws];

    // prefetch logits for the 4 rows (overlap with smem fill + sync)
    float xl[4];
    #pragma unroll
    for (int r = 0; r < 4; r++)
        xl[r] = logits[(b * H + i0 + r) * W + j];

    #pragma unroll
    for (int r = 0; r < 4; r++) {
        int i = i0 + r, bi = i & 31;
        unsigned int below = vw & (0xFFFFFFFFu >> (31 - bi));
        unsigned int above = vw & (0xFFFFFFFFu << bi);
        int last = below ? ((ws << 5) + 31 - __clz(below)) : P;
        int nxt  = above ? ((ws << 5) + __ffs(above) - 1)  : N;
        int f = min(min(i - last, nxt - i), 10000);      // BIG clip (1e4)
        u.b.s[r][j] = 1e30f;                             // left pad
        u.b.s[r][2 * W + j] = 1e30f;                     // right pad
        u.b.s[r][W + j] = (float)(f * f);                // exact in fp32
    }
    __syncthreads();

    // exact min-plus per pixel, per-lane early exit (no vote in chain)
    float sd = 0.f, sp = 0.f, mxv = 0.f;
    #pragma unroll
    for (int r = 0; r < 4; r++) {
        const float* s = u.b.s[r];
        float m = s[W + j];
        int o = 1;
        while ((float)(o * o) < m) {
            float o2 = (float)(o * o);
            m = fminf(m, s[W + j - o] + o2);
            m = fminf(m, s[W + j + o] + o2);
            o++;
        }
        float d = sqrtf(m);
        float pred = 1.f / (1.f + __expf(-xl[r]));
        sd += d;
        sp += pred * d;
        mxv = fmaxf(mxv, d);
    }

    // deterministic block reduction -> per-block partials
    #pragma unroll
    for (int o = 16; o; o >>= 1) {
        sd  += __shfl_down_sync(0xffffffffu, sd,  o);
        sp  += __shfl_down_sync(0xffffffffu, sp,  o);
        mxv  = fmaxf(mxv, __shfl_down_sync(0xffffffffu, mxv, o));
    }
    if (lane == 0) { rs[w] = sd; rp[w] = sp; rm[w] = mxv; }
    __syncthreads();
    if (tid == 0) {
        float S = 0.f, Pp = 0.f, M = 0.f;
        #pragma unroll
        for (int k = 0; k < 8; k++) { S += rs[k]; Pp += rp[k]; M = fmaxf(M, rm[k]); }
        g_d[bid] = S; g_pd[bid] = Pp; g_mx[bid] = M;
        __threadfence();
        unsigned int tk = atomicAdd(&g_ticket, 1u);
        amLast = (tk == GRID - 1);
    }
    __syncthreads();
    if (!amLast) return;

    // ================= Final reduction (last block) ==========================
    // warp wb reduces image wb's 64 block-partials (2 per lane), deterministic
    {
        int wb = w;
        double sdd = 0.0, spp = 0.0;
        float mxx = 0.f;
        #pragma unroll
        for (int k = 0; k < 2; k++) {
            int rr = wb * 64 + k * 32 + lane;
            sdd += (double)g_d[rr];
            spp += (double)g_pd[rr];
            mxx = fmaxf(mxx, g_mx[rr]);
        }
        #pragma unroll
        for (int o = 16; o; o >>= 1) {
            sdd += __shfl_down_sync(0xffffffffu, sdd, o);
            spp += __shfl_down_sync(0xffffffffu, spp, o);
            mxx  = fmaxf(mxx, __shfl_down_sync(0xffffffffu, mxx, o));
        }
        __shared__ double sper[BB];
        if (lane == 0)
            sper[wb] = spp / (sdd + 1e-7 * ((double)mxx + 1e-7));
        __syncthreads();
        if (tid == 0) {
            double acc = 0.0;
            #pragma unroll
            for (int k = 0; k < BB; k++) acc += sper[k];
            out[0] = (float)(acc / BB);
            g_ticket = 0;                 // reset for next graph replay
            g_barA = 0;
        }
    }
}

extern "C" void kernel_launch(void* const* d_in, const int* in_sizes, int n_in,
                              void* d_out, int out_size) {
    const float* logits = (const float*)d_in[0];
    const int*   target = (const int*)d_in[1];
    float* out = (float*)d_out;

    k_fused<<<GRID, 256>>>(logits, target, out);
}